// round 14
// baseline (speedup 1.0000x reference)
#include <cuda_runtime.h>
#include <cuda_bf16.h>
#include <cstdint>

constexpr int BB = 16, NN = 2048, DD = 64;
constexpr int TM = 128, TN = 128;
constexpr int THREADS = 256;          // 8 warps; warp w owns rows 16w..16w+15
constexpr int NT = NN / TN;           // 16 K-tiles
constexpr int KW = 36;                // K smem row stride in 4B words (72 bf16)
constexpr int MAIN_CTAS = 256;
constexpr int ZERO_CTAS = 64;
constexpr int TOTAL_CTAS = MAIN_CTAS + ZERO_CTAS;

__device__ int g_argmax[BB * NN];
__device__ unsigned g_count = 0;

__device__ __forceinline__ uint32_t packbf(float x, float y) {
    __nv_bfloat162 h = __floats2bfloat162_rn(x, y);
    return *reinterpret_cast<uint32_t*>(&h);
}

__device__ __forceinline__ void mma16816(float* c, const uint32_t* a,
                                         uint32_t b0, uint32_t b1) {
    asm volatile(
        "mma.sync.aligned.m16n8k16.row.col.f32.bf16.bf16.f32 "
        "{%0,%1,%2,%3}, {%4,%5,%6,%7}, {%8,%9}, {%0,%1,%2,%3};"
        : "+f"(c[0]), "+f"(c[1]), "+f"(c[2]), "+f"(c[3])
        : "r"(a[0]), "r"(a[1]), "r"(a[2]), "r"(a[3]), "r"(b0), "r"(b1));
}

__device__ __forceinline__ void ldsm_x4(uint32_t& f0, uint32_t& f1,
                                        uint32_t& f2, uint32_t& f3, uint32_t addr) {
    asm volatile("ldmatrix.sync.aligned.m8n8.x4.shared.b16 {%0,%1,%2,%3}, [%4];"
                 : "=r"(f0), "=r"(f1), "=r"(f2), "=r"(f3) : "r"(addr));
}

constexpr unsigned NEGINF_BITS = 0xFF800000u;

// Branch-free top-4 insert of a packed (score|col) float; masked -> -inf.
__device__ __forceinline__ void top4(float (&P)[4], float s, int m, int col) {
    float pf = __int_as_float((__float_as_int(s) & 0xFFFFF800) | col);
    pf = m ? __int_as_float(NEGINF_BITS) : pf;        // SEL, branch-free
    float t1 = fminf(P[0], pf); P[0] = fmaxf(P[0], pf);
    float t2 = fminf(P[1], t1); P[1] = fmaxf(P[1], t1);
    float t3 = fminf(P[2], t2); P[2] = fmaxf(P[2], t2);
    P[3] = fmaxf(P[3], t3);
}

// arrival: last CTA (after all zero-stores + g_argmax writes) scatters 1.0s
__device__ __forceinline__ void arrive_and_scatter(float* __restrict__ attn) {
    __shared__ int lastFlag;
    __syncthreads();
    if (threadIdx.x == 0) {
        __threadfence();                               // release my stores
        unsigned old = atomicAdd(&g_count, 1u);
        lastFlag = (old == (unsigned)TOTAL_CTAS - 1u);
    }
    __syncthreads();
    if (lastFlag) {
        __threadfence();                               // acquire all stores
        for (int r = threadIdx.x; r < BB * NN; r += THREADS)
            attn[(size_t)r * NN + g_argmax[r]] = 1.0f;
        if (threadIdx.x == 0) atomicExch(&g_count, 0u);  // replay-safe reset
    }
}

__global__ void __launch_bounds__(THREADS, 2)
attn_fused_kernel(const float* __restrict__ q, const float* __restrict__ kmat,
                  const float* __restrict__ v, const int* __restrict__ maski,
                  float* __restrict__ attn, float* __restrict__ outp)
{
    // ---------------- zero-CTA branch ----------------
    if (blockIdx.x >= MAIN_CTAS) {
        const long long n4 = (long long)BB * NN * NN / 4;       // 16,777,216
        const long long chunk = n4 / ZERO_CTAS;                 // 262,144
        const long long base = (long long)(blockIdx.x - MAIN_CTAS) * chunk;
        float4* attn4 = reinterpret_cast<float4*>(attn);
        const float4 z = make_float4(0.f, 0.f, 0.f, 0.f);
        for (long long i = base + threadIdx.x; i < base + chunk; i += THREADS)
            __stcs(attn4 + i, z);
        arrive_and_scatter(attn);
        return;
    }

    // ---------------- main branch (round-9 measured path) ----------------
    __shared__ __align__(16) uint32_t Ksm[TN * KW];   // bf16 K tile, 18 KB

    const int tid  = threadIdx.x;
    const int warp = tid >> 5;
    const int lane = tid & 31;
    const int g    = lane >> 2;
    const int tig  = lane & 3;
    const int b       = blockIdx.x >> 4;
    const int rowBase = (blockIdx.x & 15) * TM;
    const int r0 = rowBase + warp * 16 + g;
    const int r1 = r0 + 8;

    uint32_t sKsm;
    asm("{ .reg .u64 t; cvta.to.shared.u64 t, %1; cvt.u32.u64 %0, t; }"
        : "=r"(sKsm) : "l"(Ksm));
    const int lm_m = lane >> 3;
    const int lm_r = lane & 7;
    const uint32_t lmBase = sKsm + 4u * ((uint32_t)(8 * (lm_m >> 1) + lm_r) * KW
                                         + (uint32_t)(lm_m & 1) * 4u);

    // ---- A fragments (Q rows r0,r1 as bf16), loaded once ----
    uint32_t aF[4][4];
    {
        const float* q0 = q + ((size_t)b * NN + r0) * DD;
        const float* q1 = q + ((size_t)b * NN + r1) * DD;
        #pragma unroll
        for (int s = 0; s < 4; ++s) {
            float2 x0 = *reinterpret_cast<const float2*>(q0 + 16 * s + 2 * tig);
            float2 x1 = *reinterpret_cast<const float2*>(q1 + 16 * s + 2 * tig);
            float2 x2 = *reinterpret_cast<const float2*>(q0 + 16 * s + 2 * tig + 8);
            float2 x3 = *reinterpret_cast<const float2*>(q1 + 16 * s + 2 * tig + 8);
            aF[s][0] = packbf(x0.x, x0.y);
            aF[s][1] = packbf(x1.x, x1.y);
            aF[s][2] = packbf(x2.x, x2.y);
            aF[s][3] = packbf(x3.x, x3.y);
        }
    }

    const float NEGINF = __int_as_float(NEGINF_BITS);
    float p0[4] = {NEGINF, NEGINF, NEGINF, NEGINF};
    float p1[4] = {NEGINF, NEGINF, NEGINF, NEGINF};

    const int* mr0 = maski + ((size_t)b * NN + r0) * NN + 2 * tig;
    const int* mr1 = maski + ((size_t)b * NN + r1) * NN + 2 * tig;

    for (int t = 0; t < NT; ++t) {
        if (t) __syncthreads();

        // ---- load + convert K tile (row = tid>>1, d-half = (tid&1)*32) ----
        {
            const float4* src = reinterpret_cast<const float4*>(
                kmat + ((size_t)b * NN + t * TN + (tid >> 1)) * DD) + (tid & 1) * 8;
            uint32_t* dst = Ksm + (tid >> 1) * KW + (tid & 1) * 16;
            float4 f[8];
            #pragma unroll
            for (int i = 0; i < 8; ++i) f[i] = src[i];
            #pragma unroll
            for (int qt = 0; qt < 4; ++qt)
                *reinterpret_cast<uint4*>(dst + qt * 4) =
                    make_uint4(packbf(f[2*qt].x,   f[2*qt].y),
                               packbf(f[2*qt].z,   f[2*qt].w),
                               packbf(f[2*qt+1].x, f[2*qt+1].y),
                               packbf(f[2*qt+1].z, f[2*qt+1].w));
        }
        __syncthreads();

        #pragma unroll
        for (int jh = 0; jh < 2; ++jh) {
            const int colBase = t * TN + jh * 64;

            // mask loads first: latency hidden under LDSM+HMMA below
            int2 mA[8], mB[8];
            #pragma unroll
            for (int jj = 0; jj < 8; ++jj) {
                mA[jj] = __ldcs(reinterpret_cast<const int2*>(mr0 + colBase + 8 * jj));
                mB[jj] = __ldcs(reinterpret_cast<const int2*>(mr1 + colBase + 8 * jj));
            }

            float c[8][4];
            #pragma unroll
            for (int j = 0; j < 8; ++j)
                #pragma unroll
                for (int e = 0; e < 4; ++e) c[j][e] = 0.f;

            #pragma unroll
            for (int jp = 0; jp < 4; ++jp) {
                const uint32_t aj = lmBase + 4u * (uint32_t)((64 * jh + 16 * jp) * KW);
                #pragma unroll
                for (int s = 0; s < 4; ++s) {
                    uint32_t f0, f1, f2, f3;
                    ldsm_x4(f0, f1, f2, f3, aj + 32u * s);
                    mma16816(c[2 * jp],     aF[s], f0, f1);
                    mma16816(c[2 * jp + 1], aF[s], f2, f3);
                }
            }

            #pragma unroll
            for (int jj = 0; jj < 8; ++jj) {
                const int col = colBase + 8 * jj + 2 * tig;
                top4(p0, c[jj][0], mA[jj].x, col);
                top4(p0, c[jj][1], mA[jj].y, col + 1);
                top4(p1, c[jj][2], mB[jj].x, col);
                top4(p1, c[jj][3], mB[jj].y, col + 1);
            }
        }
    }

    // ---- exact fp32 rescore of <=4 candidates/lane (round-2-verified order) ----
    auto finish = [&](float (&P)[4], int row) {
        float bE = -__int_as_float(0x7f800000);
        int   bI = 0x7fffffff;
        #pragma unroll
        for (int i = 0; i < 4; ++i) {
            if (P[i] != NEGINF) {
                const int cI = __float_as_int(P[i]) & 0x7FF;
                const float4* qr = reinterpret_cast<const float4*>(q + ((size_t)b * NN + row) * DD);
                const float4* kr = reinterpret_cast<const float4*>(kmat + ((size_t)b * NN + cI) * DD);
                float acc = 0.f;
                #pragma unroll
                for (int j2 = 0; j2 < 16; ++j2) {
                    float4 qa = qr[j2], ka = kr[j2];
                    acc = fmaf(qa.x, ka.x, acc);
                    acc = fmaf(qa.y, ka.y, acc);
                    acc = fmaf(qa.z, ka.z, acc);
                    acc = fmaf(qa.w, ka.w, acc);
                }
                if (acc > bE || (acc == bE && cI < bI)) { bE = acc; bI = cI; }
            }
        }
        #pragma unroll
        for (int off = 1; off < 4; off <<= 1) {
            float oE = __shfl_xor_sync(0xffffffffu, bE, off);
            int   oI = __shfl_xor_sync(0xffffffffu, bI, off);
            if (oE > bE || (oE == bE && oI < bI)) { bE = oE; bI = oI; }
        }
        if (bI == 0x7fffffff) bI = 0;
        if (tig == 0) g_argmax[b * NN + row] = bI;
        const float4* vs = reinterpret_cast<const float4*>(v + ((size_t)b * NN + bI) * DD);
        float4* dst = reinterpret_cast<float4*>(outp + ((size_t)b * NN + row) * DD);
        #pragma unroll
        for (int j2 = 0; j2 < 4; ++j2) dst[tig * 4 + j2] = vs[tig * 4 + j2];
    };
    finish(p0, r0);
    finish(p1, r1);

    arrive_and_scatter(attn);
}

extern "C" void kernel_launch(void* const* d_in, const int* in_sizes, int n_in,
                              void* d_out, int out_size) {
    const float* q    = (const float*)d_in[0];
    const float* k    = (const float*)d_in[1];
    const float* v    = (const float*)d_in[2];
    const int*   mask = (const int*)d_in[3];

    float* attn = (float*)d_out;                   // [B, N, N]
    float* outp = attn + (size_t)BB * NN * NN;     // [B, N, D]

    attn_fused_kernel<<<TOTAL_CTAS, THREADS>>>(q, k, v, mask, attn, outp);
}

// round 15
// speedup vs baseline: 1.2820x; 1.2820x over previous
#include <cuda_runtime.h>
#include <cuda_bf16.h>
#include <cstdint>

constexpr int BB = 16, NN = 2048, DD = 64;
constexpr int TM = 128, TN = 128;
constexpr int THREADS = 256;          // 8 warps; warp w owns rows 16w..16w+15
constexpr int NT = NN / TN;           // 16 K-tiles
constexpr int KW = 36;                // K smem row stride in 4B words (72 bf16)

__device__ __forceinline__ uint32_t packbf(float x, float y) {
    __nv_bfloat162 h = __floats2bfloat162_rn(x, y);
    return *reinterpret_cast<uint32_t*>(&h);
}

__device__ __forceinline__ void mma16816(float* c, const uint32_t* a,
                                         uint32_t b0, uint32_t b1) {
    asm volatile(
        "mma.sync.aligned.m16n8k16.row.col.f32.bf16.bf16.f32 "
        "{%0,%1,%2,%3}, {%4,%5,%6,%7}, {%8,%9}, {%0,%1,%2,%3};"
        : "+f"(c[0]), "+f"(c[1]), "+f"(c[2]), "+f"(c[3])
        : "r"(a[0]), "r"(a[1]), "r"(a[2]), "r"(a[3]), "r"(b0), "r"(b1));
}

__device__ __forceinline__ void ldsm_x4(uint32_t& f0, uint32_t& f1,
                                        uint32_t& f2, uint32_t& f3, uint32_t addr) {
    asm volatile("ldmatrix.sync.aligned.m8n8.x4.shared.b16 {%0,%1,%2,%3}, [%4];"
                 : "=r"(f0), "=r"(f1), "=r"(f2), "=r"(f3) : "r"(addr));
}

constexpr unsigned NEGINF_BITS = 0xFF800000u;

// tile-local top-2 insert of packed (score|col); masked -> -inf falls through
__device__ __forceinline__ void ins2(float& A, float& B, float s, unsigned m, int col) {
    float pf = __int_as_float((__float_as_int(s) & 0xFFFFF800) | col);
    pf = m ? __int_as_float(NEGINF_BITS) : pf;
    float t = fminf(A, pf);
    A = fmaxf(A, pf);
    B = fmaxf(B, t);
}
// global top-4 insert of an already-packed value
__device__ __forceinline__ void ins4(float (&P)[4], float v) {
    float t1 = fminf(P[0], v); P[0] = fmaxf(P[0], v);
    float t2 = fminf(P[1], t1); P[1] = fmaxf(P[1], t1);
    float t3 = fminf(P[2], t2); P[2] = fmaxf(P[2], t2);
    P[3] = fmaxf(P[3], t3);
}

__global__ void __launch_bounds__(THREADS, 2)
attn_main_kernel(const float* __restrict__ q, const float* __restrict__ kmat,
                 const float* __restrict__ v, const int* __restrict__ maski,
                 float* __restrict__ attn, float* __restrict__ outp)
{
    __shared__ __align__(16) uint32_t Ksm[TN * KW];   // bf16 K tile, 18 KB

    const int tid  = threadIdx.x;
    const int warp = tid >> 5;
    const int lane = tid & 31;
    const int g    = lane >> 2;
    const int tig  = lane & 3;
    const int b       = blockIdx.y;
    const int rowBase = blockIdx.x * TM;
    const int r0 = rowBase + warp * 16 + g;
    const int r1 = r0 + 8;

    uint32_t sKsm;
    asm("{ .reg .u64 t; cvta.to.shared.u64 t, %1; cvt.u32.u64 %0, t; }"
        : "=r"(sKsm) : "l"(Ksm));
    const int lm_m = lane >> 3;
    const int lm_r = lane & 7;
    const uint32_t lmBase = sKsm + 4u * ((uint32_t)(8 * (lm_m >> 1) + lm_r) * KW
                                         + (uint32_t)(lm_m & 1) * 4u);

    // ---- A fragments (Q rows r0,r1 as bf16), loaded once ----
    uint32_t aF[4][4];
    {
        const float* q0 = q + ((size_t)b * NN + r0) * DD;
        const float* q1 = q + ((size_t)b * NN + r1) * DD;
        #pragma unroll
        for (int s = 0; s < 4; ++s) {
            float2 x0 = *reinterpret_cast<const float2*>(q0 + 16 * s + 2 * tig);
            float2 x1 = *reinterpret_cast<const float2*>(q1 + 16 * s + 2 * tig);
            float2 x2 = *reinterpret_cast<const float2*>(q0 + 16 * s + 2 * tig + 8);
            float2 x3 = *reinterpret_cast<const float2*>(q1 + 16 * s + 2 * tig + 8);
            aF[s][0] = packbf(x0.x, x0.y);
            aF[s][1] = packbf(x1.x, x1.y);
            aF[s][2] = packbf(x2.x, x2.y);
            aF[s][3] = packbf(x3.x, x3.y);
        }
    }

    const float NEGINF = __int_as_float(NEGINF_BITS);
    float p0[4] = {NEGINF, NEGINF, NEGINF, NEGINF};
    float p1[4] = {NEGINF, NEGINF, NEGINF, NEGINF};

    const int* mr0 = maski + ((size_t)b * NN + r0) * NN + 2 * tig;
    const int* mr1 = maski + ((size_t)b * NN + r1) * NN + 2 * tig;

    // coalesced zero-store base: warp w zeroes rows rowBase + w + 8i, lane = col/4
    float* zbase = attn + ((size_t)b * NN + rowBase + warp) * NN + 4 * lane;

    for (int t = 0; t < NT; ++t) {
        if (t) __syncthreads();

        // ---- load + convert K tile (row = tid>>1, d-half = (tid&1)*32) ----
        {
            const float4* src = reinterpret_cast<const float4*>(
                kmat + ((size_t)b * NN + t * TN + (tid >> 1)) * DD) + (tid & 1) * 8;
            uint32_t* dst = Ksm + (tid >> 1) * KW + (tid & 1) * 16;
            float4 f[8];
            #pragma unroll
            for (int i = 0; i < 8; ++i) f[i] = src[i];
            #pragma unroll
            for (int qt = 0; qt < 4; ++qt)
                *reinterpret_cast<uint4*>(dst + qt * 4) =
                    make_uint4(packbf(f[2*qt].x,   f[2*qt].y),
                               packbf(f[2*qt].z,   f[2*qt].w),
                               packbf(f[2*qt+1].x, f[2*qt+1].y),
                               packbf(f[2*qt+1].z, f[2*qt+1].w));
        }
        __syncthreads();

        float A0 = NEGINF, B0 = NEGINF, A1 = NEGINF, B1 = NEGINF;

        #pragma unroll
        for (int jh = 0; jh < 2; ++jh) {
            const int colBase = t * TN + jh * 64;

            // mask loads first: latency hidden under LDSM+HMMA below
            int2 mA[8], mB[8];
            #pragma unroll
            for (int jj = 0; jj < 8; ++jj) {
                mA[jj] = __ldcs(reinterpret_cast<const int2*>(mr0 + colBase + 8 * jj));
                mB[jj] = __ldcs(reinterpret_cast<const int2*>(mr1 + colBase + 8 * jj));
            }

            float c[8][4];
            #pragma unroll
            for (int j = 0; j < 8; ++j)
                #pragma unroll
                for (int e = 0; e < 4; ++e) c[j][e] = 0.f;

            #pragma unroll
            for (int jp = 0; jp < 4; ++jp) {
                const uint32_t aj = lmBase + 4u * (uint32_t)((64 * jh + 16 * jp) * KW);
                #pragma unroll
                for (int s = 0; s < 4; ++s) {
                    uint32_t f0, f1, f2, f3;
                    ldsm_x4(f0, f1, f2, f3, aj + 32u * s);
                    mma16816(c[2 * jp],     aF[s], f0, f1);
                    mma16816(c[2 * jp + 1], aF[s], f2, f3);
                }
            }

            #pragma unroll
            for (int jj = 0; jj < 8; ++jj) {
                const int col = colBase + 8 * jj + 2 * tig;
                ins2(A0, B0, c[jj][0], (unsigned)mA[jj].x, col);
                ins2(A0, B0, c[jj][1], (unsigned)mA[jj].y, col + 1);
                ins2(A1, B1, c[jj][2], (unsigned)mB[jj].x, col);
                ins2(A1, B1, c[jj][3], (unsigned)mB[jj].y, col + 1);
            }
        }

        ins4(p0, A0); ins4(p0, B0);
        ins4(p1, A1); ins4(p1, B1);

        // ---- coalesced attn zeroing: warp w -> rows w+8i, this tile's cols ----
        // one STG.128 per row, 32 lanes contiguous (4 lines/instruction)
        {
            float4* zp = reinterpret_cast<float4*>(zbase + t * TN);
            const float4 z = make_float4(0.f, 0.f, 0.f, 0.f);
            #pragma unroll
            for (int i = 0; i < 16; ++i)
                __stcs(zp + (size_t)(8 * i) * (NN / 4), z);
        }
    }

    __syncthreads();   // zeros (block-wide) visible before the 1.0 scatter

    // ---- exact fp32 rescore of <=4 candidates/lane (round-2-verified order) ----
    auto finish = [&](float (&P)[4], int row) {
        float bE = -__int_as_float(0x7f800000);
        int   bI = 0x7fffffff;
        #pragma unroll
        for (int i = 0; i < 4; ++i) {
            if (P[i] != NEGINF) {
                const int cI = __float_as_int(P[i]) & 0x7FF;
                const float4* qr = reinterpret_cast<const float4*>(q + ((size_t)b * NN + row) * DD);
                const float4* kr = reinterpret_cast<const float4*>(kmat + ((size_t)b * NN + cI) * DD);
                float acc = 0.f;
                #pragma unroll
                for (int j2 = 0; j2 < 16; ++j2) {
                    float4 qa = qr[j2], ka = kr[j2];
                    acc = fmaf(qa.x, ka.x, acc);
                    acc = fmaf(qa.y, ka.y, acc);
                    acc = fmaf(qa.z, ka.z, acc);
                    acc = fmaf(qa.w, ka.w, acc);
                }
                if (acc > bE || (acc == bE && cI < bI)) { bE = acc; bI = cI; }
            }
        }
        #pragma unroll
        for (int off = 1; off < 4; off <<= 1) {
            float oE = __shfl_xor_sync(0xffffffffu, bE, off);
            int   oI = __shfl_xor_sync(0xffffffffu, bI, off);
            if (oE > bE || (oE == bE && oI < bI)) { bE = oE; bI = oI; }
        }
        if (bI == 0x7fffffff) bI = 0;
        if (tig == 0) attn[((size_t)b * NN + row) * NN + bI] = 1.0f;
        const float4* vs = reinterpret_cast<const float4*>(v + ((size_t)b * NN + bI) * DD);
        float4* dst = reinterpret_cast<float4*>(outp + ((size_t)b * NN + row) * DD);
        #pragma unroll
        for (int j2 = 0; j2 < 4; ++j2) dst[tig * 4 + j2] = vs[tig * 4 + j2];
    };
    finish(p0, r0);
    finish(p1, r1);
}

extern "C" void kernel_launch(void* const* d_in, const int* in_sizes, int n_in,
                              void* d_out, int out_size) {
    const float* q    = (const float*)d_in[0];
    const float* k    = (const float*)d_in[1];
    const float* v    = (const float*)d_in[2];
    const int*   mask = (const int*)d_in[3];

    float* attn = (float*)d_out;                   // [B, N, N]
    float* outp = attn + (size_t)BB * NN * NN;     // [B, N, D]

    dim3 grid(NN / TM, BB);
    attn_main_kernel<<<grid, THREADS>>>(q, k, v, mask, attn, outp);
}